// round 11
// baseline (speedup 1.0000x reference)
#include <cuda_runtime.h>
#include <cstdint>

// CombineEmbeddings: out[b,s,:] = (idx[b,s] >= 0) ? patch[b, idx[b,s], :]
//                                                 : word[b, s, :]
// Shapes (fixed for this problem): B=4, S=4096, P=2048, H=4096, fp32.
//
// FINAL. Pure HBM-bound row copy at the traffic floor (256 MiB read +
// 256 MiB write; zero reuse is structural). Measured 6.33-6.41 TB/s
// (79-81% DRAM-active) — this part's ceiling for a 1:1 read/write
// streaming mix, established by a complete sweep:
//   access width : float4 == 256-bit LDG/STG           (80.9% vs 80.1%)
//   per-warp MLP : depth 2 / 4 / 8 -> 70.5 / 80.9 / 79.9%  (saturates at 4)
//   rows per CTA : 1 best; 2-row and 8-row-pipelined regress (L1tex queue)
//   cache hints  : .nc / .cs neutral (no reuse either way)
//   data path    : driver cudaMemcpyAsync slower (serialized CE nodes);
//                  cp.async.bulk shares the same LTS cap (path-independent)
// Issue% ~4 throughout: SMs idle, DRAM binding. Nothing left to move.
//
// Shape: one CTA per 16 KB row (16384 micro-CTAs = deepest, smoothest MC
// request stream), 256 threads, 4 front-batched float4 loads -> 4 stores,
// source pointer selected once per CTA (uniform branch, no divergence).

#define CE_B 4
#define CE_S 4096
#define CE_P 2048
#define CE_H 4096

__global__ void __launch_bounds__(256)
combine_embeddings_kernel(const float4* __restrict__ word,
                          const float4* __restrict__ patch,
                          const int*    __restrict__ idx,
                          float4*       __restrict__ out)
{
    constexpr int H4 = CE_H / 4;             // 1024 float4 per row
    const int row = blockIdx.x;              // 0 .. B*S-1
    const int b   = row >> 12;               // row / S  (S = 4096)
    const int i   = __ldg(idx + row);

    const float4* __restrict__ src =
        (i >= 0) ? (patch + ((int64_t)b * CE_P + i) * H4)
                 : (word  + (int64_t)row * H4);
    float4* __restrict__ dst = out + (int64_t)row * H4;

    // 1024 float4 / 256 threads = 4 iterations, fully unrolled:
    // all 4 loads (64 B/thread) in flight before the first store binds.
    const int t = threadIdx.x;
    float4 v0 = src[t];
    float4 v1 = src[t + 256];
    float4 v2 = src[t + 512];
    float4 v3 = src[t + 768];
    dst[t]       = v0;
    dst[t + 256] = v1;
    dst[t + 512] = v2;
    dst[t + 768] = v3;
}

extern "C" void kernel_launch(void* const* d_in, const int* in_sizes, int n_in,
                              void* d_out, int out_size)
{
    const float4* word  = (const float4*)d_in[0];   // [B, S, H] fp32
    const float4* patch = (const float4*)d_in[1];   // [B, P, H] fp32
    const int*    idx   = (const int*)d_in[2];      // [B, S] int32
    float4*       out   = (float4*)d_out;           // [B, S, H] fp32

    const int rows = CE_B * CE_S;                   // 16384
    combine_embeddings_kernel<<<rows, 256>>>(word, patch, idx, out);
}

// round 12
// speedup vs baseline: 1.0019x; 1.0019x over previous
#include <cuda_runtime.h>
#include <cstdint>

// CombineEmbeddings: out[b,s,:] = (idx[b,s] >= 0) ? patch[b, idx[b,s], :]
//                                                 : word[b, s, :]
// Shapes (fixed): B=4, S=4096, P=2048, H=4096, fp32.
//
// R12 probe: bulk-copy data path (cp.async.bulk / UBLKCP, no tensor map).
// Each CTA moves one 16 KB row as ONE bulk G->S transaction and ONE bulk
// S->G transaction — maximally long contiguous DRAM bursts, vs 128 scattered
// 128B warp requests in the LDG kernel. Tests whether the ~20% DRAM idle is
// burst-shape (activate/turnaround) overhead. LDG baseline: 82.3us, 81% DRAM.

#define CE_B 4
#define CE_S 4096
#define CE_P 2048
#define CE_H 4096
#define ROW_BYTES (CE_H * 4)   // 16384

__global__ void __launch_bounds__(32)
combine_embeddings_bulk_kernel(const float* __restrict__ word,
                               const float* __restrict__ patch,
                               const int*   __restrict__ idx,
                               float*       __restrict__ out)
{
    __shared__ alignas(128) char buf[ROW_BYTES];
    __shared__ alignas(8)  unsigned long long mbar;

    const int row = blockIdx.x;              // 0 .. B*S-1
    const int b   = row >> 12;               // row / S (S = 4096)
    const int i   = __ldg(idx + row);

    const float* __restrict__ src =
        (i >= 0) ? (patch + ((int64_t)b * CE_P + i) * CE_H)
                 : (word  + (int64_t)row * CE_H);
    float* __restrict__ dst = out + (int64_t)row * CE_H;

    uint32_t s_buf, s_mbar;
    asm("{ .reg .u64 t; cvta.to.shared.u64 t, %1; cvt.u32.u64 %0, t; }"
        : "=r"(s_buf) : "l"((void*)buf));
    asm("{ .reg .u64 t; cvta.to.shared.u64 t, %1; cvt.u32.u64 %0, t; }"
        : "=r"(s_mbar) : "l"((void*)&mbar));

    if (threadIdx.x == 0) {
        // Init barrier, make it visible to the async proxy.
        asm volatile("mbarrier.init.shared.b64 [%0], 1;" :: "r"(s_mbar) : "memory");
        asm volatile("fence.proxy.async.shared::cta;" ::: "memory");

        // Bulk load: one 16 KB global->shared transaction.
        asm volatile("mbarrier.arrive.expect_tx.shared.b64 _, [%0], %1;"
                     :: "r"(s_mbar), "r"((uint32_t)ROW_BYTES) : "memory");
        asm volatile(
            "cp.async.bulk.shared::cta.global.mbarrier::complete_tx::bytes "
            "[%0], [%1], %2, [%3];"
            :: "r"(s_buf), "l"(src), "r"((uint32_t)ROW_BYTES), "r"(s_mbar)
            : "memory");

        // Wait for the load.
        asm volatile(
            "{\n\t"
            ".reg .pred P;\n\t"
            "W_%=:\n\t"
            "mbarrier.try_wait.parity.shared.b64 P, [%0], 0, 0x989680;\n\t"
            "@P bra.uni D_%=;\n\t"
            "bra.uni W_%=;\n\t"
            "D_%=:\n\t"
            "}"
            :: "r"(s_mbar) : "memory");

        // Bulk store: one 16 KB shared->global transaction.
        asm volatile(
            "cp.async.bulk.global.shared::cta.bulk_group [%0], [%1], %2;"
            :: "l"(dst), "r"(s_buf), "r"((uint32_t)ROW_BYTES) : "memory");
        asm volatile("cp.async.bulk.commit_group;" ::: "memory");
        asm volatile("cp.async.bulk.wait_group 0;" ::: "memory");
    }
}

extern "C" void kernel_launch(void* const* d_in, const int* in_sizes, int n_in,
                              void* d_out, int out_size)
{
    const float* word  = (const float*)d_in[0];   // [B, S, H] fp32
    const float* patch = (const float*)d_in[1];   // [B, P, H] fp32
    const int*   idx   = (const int*)d_in[2];     // [B, S] int32
    float*       out   = (float*)d_out;           // [B, S, H] fp32

    const int rows = CE_B * CE_S;                 // 16384
    combine_embeddings_bulk_kernel<<<rows, 32>>>(word, patch, idx, out);
}